// round 2
// baseline (speedup 1.0000x reference)
#include <cuda_runtime.h>

// Persistent device state — must be reset by the finishing block each launch
// so the kernel is graph-replayable.
__device__ float        g_sum    = 0.f;
__device__ unsigned int g_ticket = 0u;

__device__ __forceinline__ float leaky(float v) {
    return v >= 0.f ? v : 0.2f * v;
}

// Serial D-dim dot of h-row with weight vector (float4 vectorized).
__device__ __forceinline__ float dot_row(const float* __restrict__ hrow,
                                         const float* __restrict__ w, int D) {
    const float4* __restrict__ a = (const float4*)hrow;
    const float4* __restrict__ b = (const float4*)w;
    float s = 0.f;
    int n4 = D >> 2;
    #pragma unroll 8
    for (int k = 0; k < n4; k++) {
        float4 x = a[k];
        float4 y = b[k];
        s += x.x * y.x + x.y * y.y + x.z * y.z + x.w * y.w;
    }
    return s;
}

// On edge match (src == i): e = leaky(dot(h[i],W1) + dot(h[dst],W2) + b).
// Only ~E/N (~32) threads chip-wide ever take this path; the redundant
// dot(h[i],W1) per match is L2-warm and negligible.
__device__ __forceinline__ void contribute(int i, int dst,
                                           const float* __restrict__ h,
                                           const float* __restrict__ W,
                                           float bval, int D) {
    float ssrc = dot_row(h + (size_t)i * D, W, D);
    float sdst = dot_row(h + (size_t)dst * D, W + D, D);
    atomicAdd(&g_sum, leaky(ssrc + sdst + bval));
}

// Single fused kernel:
//  - scans all edges (2 x int4 = 4 edges per thread, coalesced)
//  - matching threads accumulate into g_sum via atomics
//  - last block to arrive computes e_ij, writes out, resets state
__global__ void gat_fused(const int4* __restrict__ g4,
                          long long nPairs, int rem,
                          const int2* __restrict__ gall,
                          const float* __restrict__ h,
                          const float* __restrict__ W,
                          const float* __restrict__ bptr,
                          const int* __restrict__ ip,
                          const int* __restrict__ jp,
                          int D,
                          float* __restrict__ out) {
    const int t = threadIdx.x;
    const int i = ip[0];

    // ---- edge scan: 2 int4 per thread ----
    long long base = (long long)blockIdx.x * (2LL * blockDim.x) + t;
    long long idx0 = base;
    long long idx1 = base + blockDim.x;

    int4 p0, p1;
    bool v0 = idx0 < nPairs;
    bool v1 = idx1 < nPairs;
    if (v0) p0 = g4[idx0];
    if (v1) p1 = g4[idx1];

    float bval = bptr[0];
    if (v0) {
        if (p0.x == i) contribute(i, p0.y, h, W, bval, D);
        if (p0.z == i) contribute(i, p0.w, h, W, bval, D);
    }
    if (v1) {
        if (p1.x == i) contribute(i, p1.y, h, W, bval, D);
        if (p1.z == i) contribute(i, p1.w, h, W, bval, D);
    }
    // odd trailing edge (E odd) handled by one designated thread
    if (rem && blockIdx.x == 0 && t == 0) {
        int2 p = gall[2 * nPairs];
        if (p.x == i) contribute(i, p.y, h, W, bval, D);
    }

    // ---- grid-completion ticket ----
    __shared__ bool s_last;
    __syncthreads();
    if (t == 0) {
        __threadfence();  // release: g_sum atomics visible before ticket
        unsigned int old = atomicAdd(&g_ticket, 1u);
        s_last = (old == gridDim.x - 1u);
    }
    __syncthreads();
    if (!s_last) return;

    // ---- finishing block: compute e_ij with block reduction ----
    __threadfence();  // acquire: see all g_sum contributions
    const int j = jp[0];
    float a = 0.f, c = 0.f;
    for (int k = t; k < D; k += blockDim.x) {
        a += h[(size_t)i * D + k] * W[k];
        c += h[(size_t)j * D + k] * W[D + k];
    }
    #pragma unroll
    for (int off = 16; off > 0; off >>= 1) {
        a += __shfl_down_sync(0xffffffffu, a, off);
        c += __shfl_down_sync(0xffffffffu, c, off);
    }
    __shared__ float sa[32], sc[32];
    int w = t >> 5, lane = t & 31;
    if (lane == 0) { sa[w] = a; sc[w] = c; }
    __syncthreads();
    if (t == 0) {
        int nw = blockDim.x >> 5;
        float ta = 0.f, tc = 0.f;
        for (int k = 0; k < nw; k++) { ta += sa[k]; tc += sc[k]; }
        float e = leaky(ta + tc + bval);
        out[0] = e / g_sum;
        // reset persistent state for the next graph replay
        g_sum = 0.f;
        __threadfence();
        g_ticket = 0u;
    }
}

extern "C" void kernel_launch(void* const* d_in, const int* in_sizes, int n_in,
                              void* d_out, int out_size) {
    // metadata order: g (E*2 int32), h (N*D f32), i, j, W (2D f32), b (1 f32)
    const int*   g  = (const int*)d_in[0];
    const float* h  = (const float*)d_in[1];
    const int*   ip = (const int*)d_in[2];
    const int*   jp = (const int*)d_in[3];
    const float* W  = (const float*)d_in[4];
    const float* b  = (const float*)d_in[5];
    float* out = (float*)d_out;

    long long E = (long long)in_sizes[0] / 2;
    int D = in_sizes[4] / 2;

    long long nPairs = E / 2;          // int4 units (2 edges each)
    int rem = (int)(E & 1);

    const int block = 256;
    long long perBlock = 2LL * block;  // int4 units per block
    long long nBlocks = (nPairs + perBlock - 1) / perBlock;
    if (nBlocks < 1) nBlocks = 1;

    gat_fused<<<(unsigned)nBlocks, block>>>((const int4*)g, nPairs, rem,
                                            (const int2*)g, h, W, b, ip, jp,
                                            D, out);
}

// round 3
// speedup vs baseline: 2.1400x; 2.1400x over previous
#include <cuda_runtime.h>

// Scratch (no allocations allowed): compact list of matching dst nodes.
// Expected matches: E/N ~ 32. 8192 is a >200-sigma safety margin.
#define MAX_MATCH 8192
__device__ int g_cnt = 0;
__device__ int g_dsts[MAX_MATCH];

__device__ __forceinline__ float leaky(float v) {
    return v >= 0.f ? v : 0.2f * v;
}

// ---------------------------------------------------------------------------
// Kernel 1: minimal edge scan. One int4 (2 edges) per thread, coalesced.
// Matching threads (rare) just append dst to the list.
// ---------------------------------------------------------------------------
__global__ void __launch_bounds__(256) gat_scan(const int4* __restrict__ g4,
                                                unsigned nPairs, int rem,
                                                const int2* __restrict__ gall,
                                                const int* __restrict__ ip) {
    unsigned idx = blockIdx.x * 256u + threadIdx.x;
    int i = __ldg(ip);
    if (idx < nPairs) {
        int4 p = __ldg(&g4[idx]);
        if (p.x == i) {
            int k = atomicAdd(&g_cnt, 1);
            if (k < MAX_MATCH) g_dsts[k] = p.y;
        }
        if (p.z == i) {
            int k = atomicAdd(&g_cnt, 1);
            if (k < MAX_MATCH) g_dsts[k] = p.w;
        }
    } else if (rem && idx == nPairs) {
        int2 p = __ldg(&gall[(size_t)2 * nPairs]);  // trailing odd edge
        if (p.x == i) {
            int k = atomicAdd(&g_cnt, 1);
            if (k < MAX_MATCH) g_dsts[k] = p.y;
        }
    }
}

// ---------------------------------------------------------------------------
// Kernel 2: finish. One block, 256 threads (8 warps).
//  - block-computes s_src[i] and s_dst[j]
//  - warps sweep the match list: warp w handles entries w, w+8, ...
//    each entry: 32 lanes x float4 = full 128-dim dot with W2
//  - block-reduce partial sums, out[0] = leaky(ssrc+sdstj+b)/sum
//  - reset g_cnt for the next graph replay
// ---------------------------------------------------------------------------
__global__ void __launch_bounds__(256) gat_finish(const float* __restrict__ h,
                                                  const float* __restrict__ W,
                                                  const float* __restrict__ bptr,
                                                  const int* __restrict__ ip,
                                                  const int* __restrict__ jp,
                                                  int D,
                                                  float* __restrict__ out) {
    const int t    = threadIdx.x;
    const int lane = t & 31;
    const int w    = t >> 5;               // warp id, 0..7
    const int nW   = blockDim.x >> 5;      // 8

    const int   i    = __ldg(ip);
    const int   j    = __ldg(jp);
    const float bval = __ldg(bptr);
    const int   cnt  = g_cnt;

    __shared__ float sh_a[8], sh_c[8], sh_s[8];
    __shared__ float sh_ssrc;

    // ---- s_src[i], s_dst[j]: 256 threads over D (each does D/256 <= 1 elems
    //      when D=128; use strided loop for generality) ----
    float a = 0.f, c = 0.f;
    for (int k = t; k < D; k += blockDim.x) {
        a += h[(size_t)i * D + k] * W[k];
        c += h[(size_t)j * D + k] * W[D + k];
    }
    #pragma unroll
    for (int off = 16; off > 0; off >>= 1) {
        a += __shfl_down_sync(0xffffffffu, a, off);
        c += __shfl_down_sync(0xffffffffu, c, off);
    }
    if (lane == 0) { sh_a[w] = a; sh_c[w] = c; }
    __syncthreads();
    if (t == 0) {
        float ta = 0.f;
        for (int k = 0; k < nW; k++) ta += sh_a[k];
        sh_ssrc = ta;
    }
    __syncthreads();
    const float ssrc = sh_ssrc;

    // ---- sweep match list: warp w takes entries w, w+nW, ... ----
    // D=128: lane reads float4 at offset 4*lane (covers 128 floats exactly).
    const float4* __restrict__ w2 = (const float4*)(W + D);
    float4 wv = (4 * lane < D) ? w2[lane] : make_float4(0.f, 0.f, 0.f, 0.f);

    float psum = 0.f;
    for (int m = w; m < cnt && m < MAX_MATCH; m += nW) {
        int dst = g_dsts[m];
        float s = 0.f;
        if (4 * lane < D) {
            const float4* __restrict__ hr = (const float4*)(h + (size_t)dst * D);
            float4 hv = hr[lane];
            s = hv.x * wv.x + hv.y * wv.y + hv.z * wv.z + hv.w * wv.w;
        }
        #pragma unroll
        for (int off = 16; off > 0; off >>= 1)
            s += __shfl_down_sync(0xffffffffu, s, off);
        s = __shfl_sync(0xffffffffu, s, 0);
        if (lane == 0) psum += leaky(ssrc + s + bval);
    }
    if (lane == 0) sh_s[w] = psum;
    __syncthreads();

    if (t == 0) {
        float sum = 0.f, tc = 0.f;
        for (int k = 0; k < nW; k++) { sum += sh_s[k]; tc += sh_c[k]; }
        float e = leaky(ssrc + tc + bval);
        out[0] = e / sum;
        g_cnt = 0;  // reset for next graph replay
    }
}

extern "C" void kernel_launch(void* const* d_in, const int* in_sizes, int n_in,
                              void* d_out, int out_size) {
    // metadata order: g (E*2 int32), h (N*D f32), i, j, W (2D f32), b (1 f32)
    const int*   g  = (const int*)d_in[0];
    const float* h  = (const float*)d_in[1];
    const int*   ip = (const int*)d_in[2];
    const int*   jp = (const int*)d_in[3];
    const float* W  = (const float*)d_in[4];
    const float* b  = (const float*)d_in[5];
    float* out = (float*)d_out;

    long long E = (long long)in_sizes[0] / 2;
    int D = in_sizes[4] / 2;

    unsigned nPairs = (unsigned)(E / 2);   // int4 units (2 edges each)
    int rem = (int)(E & 1);

    unsigned nThreads = nPairs + (rem ? 1u : 0u);
    unsigned nBlocks  = (nThreads + 255u) / 256u;
    if (nBlocks < 1u) nBlocks = 1u;

    gat_scan<<<nBlocks, 256>>>((const int4*)g, nPairs, rem, (const int2*)g, ip);
    gat_finish<<<1, 256>>>(h, W, b, ip, jp, D, out);
}

// round 4
// speedup vs baseline: 2.4956x; 1.1662x over previous
#include <cuda_runtime.h>

// Scratch (no allocations allowed): compact list of matching dst nodes.
#define MAX_MATCH 8192
__device__ int g_cnt = 0;
__device__ int g_dsts[MAX_MATCH];

__device__ __forceinline__ float leaky(float v) {
    return v >= 0.f ? v : 0.2f * v;
}

// ---------------------------------------------------------------------------
// Kernel 1: minimal edge scan. 2 x int4 (4 edges) per thread, coalesced.
// ---------------------------------------------------------------------------
__global__ void __launch_bounds__(256) gat_scan(const int4* __restrict__ g4,
                                                unsigned nPairs, int rem,
                                                const int2* __restrict__ gall,
                                                const int* __restrict__ ip) {
    const unsigned t = threadIdx.x;
    const unsigned base = blockIdx.x * 512u + t;
    const int i = __ldg(ip);

    int4 p0, p1;
    const bool v0 = base < nPairs;
    const bool v1 = (base + 256u) < nPairs;
    if (v0) p0 = __ldg(&g4[base]);
    if (v1) p1 = __ldg(&g4[base + 256u]);

    if (v0) {
        if (p0.x == i) { int k = atomicAdd(&g_cnt, 1); if (k < MAX_MATCH) g_dsts[k] = p0.y; }
        if (p0.z == i) { int k = atomicAdd(&g_cnt, 1); if (k < MAX_MATCH) g_dsts[k] = p0.w; }
    }
    if (v1) {
        if (p1.x == i) { int k = atomicAdd(&g_cnt, 1); if (k < MAX_MATCH) g_dsts[k] = p1.y; }
        if (p1.z == i) { int k = atomicAdd(&g_cnt, 1); if (k < MAX_MATCH) g_dsts[k] = p1.w; }
    }
    if (rem && blockIdx.x == 0 && t == 0) {
        int2 p = __ldg(&gall[(size_t)2 * nPairs]);   // trailing odd edge
        if (p.x == i) { int k = atomicAdd(&g_cnt, 1); if (k < MAX_MATCH) g_dsts[k] = p.y; }
    }
}

// Warp-collective dot of a D-float row with a weight vector (float4 per lane).
__device__ __forceinline__ float warp_dot(const float* __restrict__ row,
                                          const float* __restrict__ wvec,
                                          int D, int lane) {
    float s = 0.f;
    for (int k = 4 * lane; k < D; k += 128) {
        float4 a = *(const float4*)(row + k);
        float4 b = *(const float4*)(wvec + k);
        s += a.x * b.x + a.y * b.y + a.z * b.z + a.w * b.w;
    }
    #pragma unroll
    for (int off = 16; off > 0; off >>= 1)
        s += __shfl_down_sync(0xffffffffu, s, off);
    return s;   // valid on lane 0
}

// ---------------------------------------------------------------------------
// Kernel 2: finish. One block, 1024 threads (32 warps).
//  - warp w computes raw dots for match entries w and w+32 (parallel latency)
//  - warps 0/1 also compute s_src[i], s_dst[j]
//  - 2-warp leaky+sum reduction; rare overflow loop for cnt > 64
// ---------------------------------------------------------------------------
__global__ void __launch_bounds__(1024) gat_finish(const float* __restrict__ h,
                                                   const float* __restrict__ W,
                                                   const float* __restrict__ bptr,
                                                   const int* __restrict__ ip,
                                                   const int* __restrict__ jp,
                                                   int D,
                                                   float* __restrict__ out) {
    const int t = threadIdx.x;
    const int lane = t & 31;
    const int w = t >> 5;                  // 0..31

    const int   cnt  = g_cnt;
    const int   i    = __ldg(ip);
    const int   j    = __ldg(jp);
    const float bval = __ldg(bptr);

    __shared__ float sh_s[64];
    __shared__ float sh_extra[32];
    __shared__ float sh_r[2];
    __shared__ float sh_ssrc, sh_sdstj;

    // ---- phase 1: all independent dot chains in flight simultaneously ----
    const int m0 = w, m1 = w + 32;
    float s0 = 0.f, s1 = 0.f;
    if (m0 < cnt) s0 = warp_dot(h + (size_t)g_dsts[m0] * D, W + D, D, lane);
    if (m1 < cnt) s1 = warp_dot(h + (size_t)g_dsts[m1] * D, W + D, D, lane);
    if (lane == 0) { sh_s[m0] = s0; sh_s[m1] = s1; }

    if (w == 0) {
        float s = warp_dot(h + (size_t)i * D, W, D, lane);
        if (lane == 0) sh_ssrc = s;
    } else if (w == 1) {
        float s = warp_dot(h + (size_t)j * D, W + D, D, lane);
        if (lane == 0) sh_sdstj = s;
    }
    __syncthreads();

    const float ssrc = sh_ssrc;

    // ---- phase 2a: leaky+sum over first min(cnt,64) entries (2 warps) ----
    if (w < 2) {
        int top = cnt < 64 ? cnt : 64;
        float v = (t < top) ? leaky(ssrc + sh_s[t] + bval) : 0.f;
        #pragma unroll
        for (int off = 16; off > 0; off >>= 1)
            v += __shfl_down_sync(0xffffffffu, v, off);
        if (lane == 0) sh_r[w] = v;
    }

    // ---- phase 2b: rare overflow (cnt > 64) ----
    float pex = 0.f;
    for (int m = 64 + w; m < cnt && m < MAX_MATCH; m += 32) {
        float s = warp_dot(h + (size_t)g_dsts[m] * D, W + D, D, lane);
        if (lane == 0) pex += leaky(ssrc + s + bval);
    }
    if (lane == 0) sh_extra[w] = pex;
    __syncthreads();

    if (t == 0) {
        float sum = sh_r[0] + sh_r[1];
        if (cnt > 64)
            for (int k = 0; k < 32; k++) sum += sh_extra[k];
        float e = leaky(ssrc + sh_sdstj + bval);
        out[0] = e / sum;
        g_cnt = 0;   // reset for next graph replay
    }
}

extern "C" void kernel_launch(void* const* d_in, const int* in_sizes, int n_in,
                              void* d_out, int out_size) {
    // metadata order: g (E*2 int32), h (N*D f32), i, j, W (2D f32), b (1 f32)
    const int*   g  = (const int*)d_in[0];
    const float* h  = (const float*)d_in[1];
    const int*   ip = (const int*)d_in[2];
    const int*   jp = (const int*)d_in[3];
    const float* W  = (const float*)d_in[4];
    const float* b  = (const float*)d_in[5];
    float* out = (float*)d_out;

    long long E = (long long)in_sizes[0] / 2;
    int D = in_sizes[4] / 2;

    unsigned nPairs = (unsigned)(E / 2);   // int4 units (2 edges each)
    int rem = (int)(E & 1);

    unsigned nBlocks = (nPairs + 511u) / 512u;
    if (nBlocks < 1u) nBlocks = 1u;

    gat_scan<<<nBlocks, 256>>>((const int4*)g, nPairs, rem, (const int2*)g, ip);
    gat_finish<<<1, 1024>>>(h, W, b, ip, jp, D, out);
}